// round 12
// baseline (speedup 1.0000x reference)
#include <cuda_runtime.h>

#define N 2048
#define K 16
#define BATCH 16384
#define THREADS 512
#define NG 8                      // rho groups of 16
#define CHUNKS 38                 // batch chunks -> 2 CTAs per SM
#define GRID (NG * CHUNKS)        // 304
#define TROWS 64                  // rows per tile
#define NRT (BATCH / TROWS)       // 256 row-tiles
#define STAGES 11
#define INFLIGHT 9                // wait_group 9 -> oldest of 10 pending done

// smem layout (floats): W 4096 | bias 256 | rings 16*11*128 = 22528
#define SM_WF 0
#define SM_B  4096
#define SM_R  (4096 + 256)
#define SM_TOT (SM_R + 16 * STAGES * 128)   // 26880 floats = 105 KB

// ---------------------------------------------------------------------------
// helpers
// ---------------------------------------------------------------------------
__device__ __forceinline__ unsigned long long fma2(unsigned long long a,
                                                   unsigned long long b,
                                                   unsigned long long c) {
    unsigned long long d;
    asm("fma.rn.f32x2 %0, %1, %2, %3;" : "=l"(d) : "l"(a), "l"(b), "l"(c));
    return d;
}
__device__ __forceinline__ unsigned long long dup2(float v) {
    unsigned long long r;
    asm("mov.b64 %0, {%1, %1};" : "=l"(r) : "f"(v));
    return r;
}
__device__ __forceinline__ void unpack2(unsigned long long v, float& lo, float& hi) {
    asm("mov.b64 {%0, %1}, %2;" : "=f"(lo), "=f"(hi) : "l"(v));
}
__device__ __forceinline__ void cp_async16(unsigned smem_addr, const void* gptr) {
    asm volatile("cp.async.cg.shared.global [%0], [%1], 16;"
                 :: "r"(smem_addr), "l"(gptr) : "memory");
}
__device__ __forceinline__ void cp_commit() {
    asm volatile("cp.async.commit_group;" ::: "memory");
}
__device__ __forceinline__ void cp_wait() {
    asm volatile("cp.async.wait_group %0;" :: "n"(INFLIGHT) : "memory");
}

// ---------------------------------------------------------------------------
// Single persistent kernel. CTA = (g = blockIdx.x & 7, chunk = blockIdx.x >> 3).
//   rho window: [16g, 16g+16); batch: 6-7 tiles of 64 rows.
//
// Phase A (in-CTA, no cross-CTA sync): compose this CTA's Wfin slice
//   Wfin = scaling*(W0@W1@W2); pattern c=(r+128s+3)%N; r=16g+rho+128t, m=(t+s)&15
//   -> smem [t][m4][rho][4] (16 KB). w01 staged in the ring area (scratch).
// Phase B: y[row, (16g+rho+3+128m)&2047] = sum_t x[row,16g+rho+128t]*W[t][m][rho]
//   16 warp-private 11-stage cp.async rings (512 B/stage = warp's 4 rows x 2 t),
//   no block barriers, predicated refill (no dummy tail reads), 2 rows/thread,
//   f32x2 accumulators over m-pairs (W float4 IS two fma2 operands).
// 2 CTAs/SM (105 KB smem, <=64 regs) -> 32 warps/SM.
// ---------------------------------------------------------------------------
__global__ void __launch_bounds__(THREADS, 2)
k_all(const float* __restrict__ x, const float* __restrict__ bias,
      float* __restrict__ y,
      const float* __restrict__ v0, const float* __restrict__ v1,
      const float* __restrict__ v2, const float* __restrict__ scaling) {
    extern __shared__ float sm[];
    const int tid = threadIdx.x;
    const int g   = blockIdx.x & 7;
    const int ch  = blockIdx.x >> 3;
    const int ntiles = (ch < 28) ? 7 : 6;                 // 28*7 + 10*6 = 256
    const int rt0    = (ch < 28) ? ch * 7 : 196 + (ch - 28) * 6;

    // ---------------- Phase A: compose W slice ----------------
    {
        float* w01 = sm + SM_R;                 // scratch (4096 fl) in ring area
        const int s  = tid & 15;
        const int rr = tid >> 4;                // 0..31
#pragma unroll
        for (int rb = 0; rb < 8; rb++) {
            int rl = rb * 32 + rr;              // r_local = t*16 + rho
            int r  = 16 * g + (rl & 15) + 128 * (rl >> 4);
            float a = 0.f;
#pragma unroll
            for (int k0 = 0; k0 < 16; k0++) {
                int ar = (r + 128 * k0) & (N - 1);
                a = fmaf(v0[r * 16 + k0], v1[ar * 16 + ((s - k0) & 15)], a);
            }
            w01[rl * 16 + s] = a;
        }
        __syncthreads();
        const float sc = scaling[0];
#pragma unroll
        for (int rb = 0; rb < 8; rb++) {
            int rl = rb * 32 + rr;
            int r  = 16 * g + (rl & 15) + 128 * (rl >> 4);
            float a = 0.f;
#pragma unroll
            for (int s01 = 0; s01 < 16; s01++) {
                int br = (r + 128 * s01 + 1) & (N - 1);
                a = fmaf(w01[rl * 16 + s01], v2[br * 16 + ((s - s01) & 15)], a);
            }
            int t = rl >> 4, rho = rl & 15, m = (t + s) & 15;
            sm[SM_WF + ((t * 4 + (m >> 2)) * 16 + rho) * 4 + (m & 3)] = sc * a;
        }
        if (tid < 256) {                        // bias for this CTA's 256 cols
            int m = tid >> 4, rho = tid & 15;
            sm[SM_B + tid] = bias[(16 * g + rho + 3 + 128 * m) & (N - 1)];
        }
        __syncthreads();
    }

    // ---------------- Phase B: main loop ----------------
    const int lane = tid & 31;
    const int w    = tid >> 5;
    const int b    = (lane >> 4) & 1;           // row-pair select within warp
    const int rho  = lane & 15;
    const int colb = 16 * g + rho + 3;

    // cp.async lane mapping: 4 rows x 2 t x 4 chunks of 16 B = 512 B/stage
    const int irowq = lane >> 3;                // 0..3
    const int itp   = (lane >> 2) & 1;          // t within stage
    const int ic16  = lane & 3;                 // 16B chunk within 64B
    const size_t ilane = (size_t)(4 * w + irowq) * N + 16 * g + 128 * itp + 4 * ic16;

    float* ring = sm + SM_R + w * (STAGES * 128);
    const unsigned ring_sa = (unsigned)__cvta_generic_to_shared(ring)
                           + (unsigned)((itp * 64 + irowq * 16 + ic16 * 4) * 4);

    const size_t rowbase0 = (size_t)rt0 * TROWS * N;
    const int total_stages = ntiles * 8;        // 8 stages (16 t) per tile

    // Prologue: stages 0..9 (always valid: ntiles >= 6 > 2)
    int islot = 0;
#pragma unroll
    for (int gs = 0; gs < STAGES - 1; gs++) {
        size_t off = rowbase0 + (size_t)(gs >> 3) * (TROWS * (size_t)N)
                   + ilane + (size_t)(gs & 7) * 256;
        cp_async16(ring_sa + (unsigned)(islot * 512), x + off);
        cp_commit();
        islot++;
    }
    int gs_issue = STAGES - 1;                  // next stage to issue
    int cslot = 0;

    const float* Wb = sm + SM_WF + rho * 4;
    const float* bs = sm + SM_B;

    for (int tile = 0; tile < ntiles; tile++) {
        const size_t rowoff = rowbase0 + (size_t)tile * TROWS * N;
        unsigned long long acc[2][8];
#pragma unroll
        for (int i = 0; i < 2; i++)
#pragma unroll
            for (int j = 0; j < 8; j++) acc[i][j] = 0ull;

#pragma unroll
        for (int q = 0; q < 8; q++) {
            cp_wait();
            __syncwarp();

            // Predicated refill (no dummy tail reads); commit unconditionally
            if (gs_issue < total_stages) {
                size_t off = rowbase0 + (size_t)(gs_issue >> 3) * (TROWS * (size_t)N)
                           + ilane + (size_t)(gs_issue & 7) * 256;
                cp_async16(ring_sa + (unsigned)(islot * 512), x + off);
            }
            cp_commit();
            gs_issue++;
            islot = (islot == STAGES - 1) ? 0 : islot + 1;

            const float* xs = ring + cslot * 128 + b * 32;
#pragma unroll
            for (int tp = 0; tp < 2; tp++) {
                const int t = q * 2 + tp;
                unsigned long long p0 = dup2(xs[tp * 64 + rho]);        // row 4w+2b
                unsigned long long p1 = dup2(xs[tp * 64 + 16 + rho]);   // row 4w+2b+1
                const float* wr = Wb + t * 256;
#pragma unroll
                for (int m4 = 0; m4 < 4; m4++) {
                    ulonglong2 wv = *(const ulonglong2*)(wr + m4 * 64);
                    acc[0][2 * m4]     = fma2(p0, wv.x, acc[0][2 * m4]);
                    acc[1][2 * m4]     = fma2(p1, wv.x, acc[1][2 * m4]);
                    acc[0][2 * m4 + 1] = fma2(p0, wv.y, acc[0][2 * m4 + 1]);
                    acc[1][2 * m4 + 1] = fma2(p1, wv.y, acc[1][2 * m4 + 1]);
                }
            }
            cslot = (cslot == STAGES - 1) ? 0 : cslot + 1;
        }

        // Epilogue: 2 rows x 16 m, bias + relu + streaming stores
        float* y0 = y + rowoff + (size_t)(4 * w + 2 * b) * N;
        float* y1 = y0 + N;
#pragma unroll
        for (int m2 = 0; m2 < 8; m2++) {
            int cA = (colb + 256 * m2) & (N - 1);
            int cB = (cA + 128) & (N - 1);
            float bA = bs[(2 * m2) * 16 + rho];
            float bB = bs[(2 * m2 + 1) * 16 + rho];
            float l0, h0, l1, h1;
            unpack2(acc[0][m2], l0, h0);
            unpack2(acc[1][m2], l1, h1);
            __stcs(y0 + cA, fmaxf(l0 + bA, 0.f));
            __stcs(y0 + cB, fmaxf(h0 + bB, 0.f));
            __stcs(y1 + cA, fmaxf(l1 + bA, 0.f));
            __stcs(y1 + cB, fmaxf(h1 + bB, 0.f));
        }
    }
}

// ---------------------------------------------------------------------------
// Launch: ONE kernel. Inputs: x, vals0, vals1, vals2, rows0, cols0, rows1,
//         cols1, rows2, cols2, scaling, bias
// ---------------------------------------------------------------------------
extern "C" void kernel_launch(void* const* d_in, const int* in_sizes, int n_in,
                              void* d_out, int out_size) {
    const float* x       = (const float*)d_in[0];
    const float* v0      = (const float*)d_in[1];
    const float* v1      = (const float*)d_in[2];
    const float* v2      = (const float*)d_in[3];
    const float* scaling = (const float*)d_in[10];
    const float* bias    = (const float*)d_in[11];
    float* y = (float*)d_out;

    cudaFuncSetAttribute(k_all, cudaFuncAttributeMaxDynamicSharedMemorySize,
                         SM_TOT * sizeof(float));
    k_all<<<GRID, THREADS, SM_TOT * sizeof(float)>>>(
        x, bias, y, v0, v1, v2, scaling);
}

// round 14
// speedup vs baseline: 1.4837x; 1.4837x over previous
#include <cuda_runtime.h>

#define N 2048
#define K 16
#define BATCH 16384
#define RPB 16
#define THREADS 512
#define GRID_MAIN 152
#define NTILES (BATCH / RPB)
#define STAGES 8
#define INFLIGHT 6   // wait_group 6 -> 7 groups (3.5 KB) in flight per warp

// Final composed weights, layout [t][m4][rho][4]:
//   g_Wfin[((t*4 + (m>>2))*128 + rho)*4 + (m&3)]
__device__ float g_Wfin[K * K * 128];

// ---------------------------------------------------------------------------
// PDL primitives
// ---------------------------------------------------------------------------
__device__ __forceinline__ void pdl_launch_dependents() {
    asm volatile("griddepcontrol.launch_dependents;" ::: "memory");
}
__device__ __forceinline__ void pdl_wait() {
    asm volatile("griddepcontrol.wait;" ::: "memory");
}

// ---------------------------------------------------------------------------
// Fused precompute: Wfin = scaling * (W0 @ W1 @ W2).
// 128-thread blocks (8 r x 16 s), capped at 32 regs so ONE compose CTA fits
// in the 4096-register hole left by the 120-reg main kernel -> true PDL
// overlap. launch_dependents fires first so k_main starts placing while
// compose runs.
// Composed pattern: c = (r + 128*s + 3) % N; r = rho + 128*t, m = (t+s)&15.
// ---------------------------------------------------------------------------
__global__ void __maxnreg__(32) k_compose(
        const float* __restrict__ v0, const float* __restrict__ v1,
        const float* __restrict__ v2, const float* __restrict__ scaling) {
    pdl_launch_dependents();

    __shared__ float w01[8][17];
    int s  = threadIdx.x & 15;
    int rl = threadIdx.x >> 4;                  // 0..7
    int r  = blockIdx.x * 8 + rl;

    float acc = 0.f;
#pragma unroll
    for (int k0 = 0; k0 < K; k0++) {
        int arow = (r + 128 * k0) & (N - 1);
        acc = fmaf(v0[r * K + k0], v1[arow * K + ((s - k0) & (K - 1))], acc);
    }
    w01[rl][s] = acc;
    __syncthreads();

    float sc = scaling[0];
    float acc2 = 0.f;
#pragma unroll
    for (int s01 = 0; s01 < K; s01++) {
        int brow = (r + 128 * s01 + 1) & (N - 1);
        acc2 = fmaf(w01[rl][s01], v2[brow * K + ((s - s01) & (K - 1))], acc2);
    }
    int rho = r & 127;
    int t   = r >> 7;
    int m   = (t + s) & (K - 1);
    g_Wfin[((t * 4 + (m >> 2)) * 128 + rho) * 4 + (m & 3)] = sc * acc2;
}

// ---------------------------------------------------------------------------
// Packed f32x2 + cp.async helpers
// ---------------------------------------------------------------------------
__device__ __forceinline__ unsigned long long fma2(unsigned long long a,
                                                   unsigned long long b,
                                                   unsigned long long c) {
    unsigned long long d;
    asm("fma.rn.f32x2 %0, %1, %2, %3;" : "=l"(d) : "l"(a), "l"(b), "l"(c));
    return d;
}
__device__ __forceinline__ unsigned long long dup2(float v) {
    unsigned long long r;
    asm("mov.b64 %0, {%1, %1};" : "=l"(r) : "f"(v));
    return r;
}
__device__ __forceinline__ void unpack2(unsigned long long v, float& lo, float& hi) {
    asm("mov.b64 {%0, %1}, %2;" : "=f"(lo), "=f"(hi) : "l"(v));
}
__device__ __forceinline__ void cp_async16(unsigned smem_addr, const void* gptr) {
    asm volatile("cp.async.cg.shared.global [%0], [%1], 16;"
                 :: "r"(smem_addr), "l"(gptr) : "memory");
}
__device__ __forceinline__ void cp_commit() {
    asm volatile("cp.async.commit_group;" ::: "memory");
}
__device__ __forceinline__ void cp_wait() {
    asm volatile("cp.async.wait_group %0;" :: "n"(INFLIGHT) : "memory");
}

// ---------------------------------------------------------------------------
// Persistent main kernel: y = relu(x @ Wfin + bias).
//   y[row, (rho+3+128m)&2047] = sum_t x[row, rho+128t] * Wfin[t][m][rho]
//
// __maxnreg__(120) (no __launch_bounds__ — the two are mutually exclusive;
// 1 CTA/SM is already forced by the 200 KB smem footprint): 512 x 120 =
// 61440 regs, leaving 4096 for one co-resident 128-thr/32-reg compose CTA.
// Prologue (x prefetch, W-independent) runs before griddepcontrol.wait, so
// compose executes inside the prefetch shadow.
//
// Main loop = validated R6 config: 16 warp-private 8-stage cp.async rings
// (512 B/stage), no block barriers, W resident in smem ([t][m4][rho][4] ->
// float4 IS two fma2 operands), __stcs epilogue (warp-contiguous 128 B runs).
// ---------------------------------------------------------------------------
#define SM_W      0
#define SM_X      (32 * 1024)                       // floats
#define SM_BIAS   (SM_X + 16 * STAGES * 128)        // + 16384 = 49152
#define SM_FLOATS (SM_BIAS + N)                     // 51200 floats = 200 KB

__global__ void __maxnreg__(120)
k_main(const float* __restrict__ x, const float* __restrict__ bias,
       float* __restrict__ y) {
    extern __shared__ float smem[];

    const int tid  = threadIdx.x;
    const int lane = tid & 31;
    const int warp = tid >> 5;
    const int grp  = warp >> 2;                 // 0..3 -> rows grp*4..grp*4+3
    const int wsub = warp & 3;                  // 32-rho window
    const int rho  = wsub * 32 + lane;
    const int crow = lane >> 3;                 // row this lane copies (0..3)
    const int coff = (lane & 7) * 4;            // float offset in 32-float window

    float* ring = smem + SM_X + warp * (STAGES * 128);
    const unsigned ring_sa = (unsigned)__cvta_generic_to_shared(ring)
                           + (unsigned)(crow * 32 + coff) * 4;
    const size_t lane_off = (size_t)(grp * 4 + crow) * N + wsub * 32 + coff;
    const size_t tile_step = (size_t)GRID_MAIN * RPB * N;

    int tile = blockIdx.x;
    const float* cur = x + (size_t)tile * RPB * N + lane_off;

    // Prologue FIRST (independent of Wfin): stages 0..6, 7 groups in flight.
    // Runs concurrently with k_compose under PDL.
#pragma unroll
    for (int s = 0; s < STAGES - 1; s++) {
        cp_async16(ring_sa + (unsigned)(s * 512), cur + s * 128);
        cp_commit();
    }

    // Bias is also compose-independent: load it before the wait.
    for (int i = tid; i < N; i += THREADS) smem[SM_BIAS + i] = bias[i];

    // Wait for k_compose to fully complete (g_Wfin visible)
    pdl_wait();

    // Resident W (float4)
    {
        const float4* src = (const float4*)g_Wfin;
        float4* dst = (float4*)(smem + SM_W);
#pragma unroll
        for (int i = tid; i < (K * K * 128) / 4; i += THREADS) dst[i] = src[i];
    }
    __syncthreads();

    for (; tile < NTILES; tile += GRID_MAIN) {
        const bool has_next = (tile + GRID_MAIN) < NTILES;
        const float* nxt = has_next ? cur + tile_step : cur;  // clamp: dummy re-read

        unsigned long long acc[4][8];
#pragma unroll
        for (int j = 0; j < 4; j++)
#pragma unroll
            for (int p = 0; p < 8; p++) acc[j][p] = 0ull;

#pragma unroll
        for (int t = 0; t < 16; t++) {
            cp_wait();
            __syncwarp();

            const float* xs = ring + (t & (STAGES - 1)) * 128;
            unsigned long long px0 = dup2(xs[lane]);
            unsigned long long px1 = dup2(xs[32 + lane]);
            unsigned long long px2 = dup2(xs[64 + lane]);
            unsigned long long px3 = dup2(xs[96 + lane]);

            // Refill: global stage t+7 (rolls into next tile at the tail)
            {
                const int s7 = t + (STAGES - 1);
                const float* src = (s7 < 16) ? (cur + s7 * 128)
                                             : (nxt + (s7 - 16) * 128);
                cp_async16(ring_sa + (unsigned)((s7 & (STAGES - 1)) * 512), src);
                cp_commit();
            }

            const float* wrow = smem + SM_W + t * 2048 + rho * 4;
#pragma unroll
            for (int m4 = 0; m4 < 4; m4++) {
                // float4 = two f32x2 operands for (m, m+1): no repacking
                ulonglong2 w = *(const ulonglong2*)(wrow + m4 * 512);
                acc[0][2 * m4]     = fma2(px0, w.x, acc[0][2 * m4]);
                acc[1][2 * m4]     = fma2(px1, w.x, acc[1][2 * m4]);
                acc[2][2 * m4]     = fma2(px2, w.x, acc[2][2 * m4]);
                acc[3][2 * m4]     = fma2(px3, w.x, acc[3][2 * m4]);
                acc[0][2 * m4 + 1] = fma2(px0, w.y, acc[0][2 * m4 + 1]);
                acc[1][2 * m4 + 1] = fma2(px1, w.y, acc[1][2 * m4 + 1]);
                acc[2][2 * m4 + 1] = fma2(px2, w.y, acc[2][2 * m4 + 1]);
                acc[3][2 * m4 + 1] = fma2(px3, w.y, acc[3][2 * m4 + 1]);
            }
        }
        cur = nxt;

        // Epilogue: bias + relu + streaming stores (warp-contiguous 128 B runs)
        float* yr = y + ((size_t)tile * RPB + grp * 4) * N;
#pragma unroll
        for (int p = 0; p < 8; p++) {
            const int c0 = (rho + 3 + 256 * p) & (N - 1);
            const int c1 = (c0 + 128) & (N - 1);
            const float b0 = smem[SM_BIAS + c0];
            const float b1 = smem[SM_BIAS + c1];
#pragma unroll
            for (int j = 0; j < 4; j++) {
                float lo, hi;
                unpack2(acc[j][p], lo, hi);
                __stcs(yr + (size_t)j * N + c0, fmaxf(lo + b0, 0.f));
                __stcs(yr + (size_t)j * N + c1, fmaxf(hi + b1, 0.f));
            }
        }
    }
}

// ---------------------------------------------------------------------------
// Launch: compose (128-thr blocks), then main with PDL.
// Inputs: x, vals0, vals1, vals2, rows0, cols0, rows1, cols1, rows2, cols2,
//         scaling, bias
// ---------------------------------------------------------------------------
extern "C" void kernel_launch(void* const* d_in, const int* in_sizes, int n_in,
                              void* d_out, int out_size) {
    const float* x       = (const float*)d_in[0];
    const float* v0      = (const float*)d_in[1];
    const float* v1      = (const float*)d_in[2];
    const float* v2      = (const float*)d_in[3];
    const float* scaling = (const float*)d_in[10];
    const float* bias    = (const float*)d_in[11];
    float* y = (float*)d_out;

    k_compose<<<N / 8, 128>>>(v0, v1, v2, scaling);

    static int smem_set = 0;
    if (!smem_set) {
        cudaFuncSetAttribute(k_main, cudaFuncAttributeMaxDynamicSharedMemorySize,
                             SM_FLOATS * sizeof(float));
        smem_set = 1;
    }

    cudaLaunchConfig_t cfg = {};
    cfg.gridDim = dim3(GRID_MAIN, 1, 1);
    cfg.blockDim = dim3(THREADS, 1, 1);
    cfg.dynamicSmemBytes = SM_FLOATS * sizeof(float);
    cfg.stream = 0;
    cudaLaunchAttribute attr[1];
    attr[0].id = cudaLaunchAttributeProgrammaticStreamSerialization;
    attr[0].val.programmaticStreamSerializationAllowed = 1;
    cfg.attrs = attr;
    cfg.numAttrs = 1;
    cudaLaunchKernelEx(&cfg, k_main, x, bias, y);
}